// round 6
// baseline (speedup 1.0000x reference)
#include <cuda_runtime.h>
#include <cuda_fp16.h>
#include <cstdint>

#define NTOK 8192
#define CDIM 1024
#define HDIM 4096
#define NEXP 8
#define NPAIR (NTOK * 2)
#define MAXTILES 160

// ---------------- scratch (device globals; no allocs allowed) ----------------
__device__ __half g_h[(size_t)(NPAIR + 128) * HDIM];   // gelu(x@W1), fp16 (padded rows)
__device__ float  g_y[(size_t)NPAIR * CDIM];           // (h@W2) per pair
__device__ __half g_xh[(size_t)(NPAIR + 128) * CDIM];  // gathered x rows, fp16 (padded)
__device__ __half g_w1h[(size_t)NEXP * CDIM * HDIM];   // W1 fp16
__device__ __half g_w2h[(size_t)NEXP * HDIM * CDIM];   // W2 fp16
__device__ int    g_counts[NEXP];
__device__ int    g_cnt2[NEXP];
__device__ int    g_offsets[NEXP];
__device__ int    g_tope[NPAIR];
__device__ float  g_topg[NPAIR];
__device__ int    g_pair_token[NPAIR];
__device__ int    g_pair_of_token[NPAIR];
__device__ int    g_tile_e[MAXTILES];
__device__ int    g_tile_mt[MAXTILES];
__device__ int    g_total_tiles;

// ---------------- helpers ----------------
__device__ __forceinline__ uint32_t pk(float lo, float hi) {
    uint32_t u;
    asm("cvt.rn.f16x2.f32 %0, %1, %2;" : "=r"(u) : "f"(hi), "f"(lo));
    return u;
}

__device__ __forceinline__ uint32_t smem_u32(const void* p) {
    uint32_t a;
    asm("{ .reg .u64 t; cvta.to.shared.u64 t, %1; cvt.u32.u64 %0, t; }" : "=r"(a) : "l"(p));
    return a;
}

__device__ __forceinline__ void cp16(uint32_t dst, const void* src) {
    asm volatile("cp.async.cg.shared.global [%0], [%1], 16;" :: "r"(dst), "l"(src));
}

__device__ __forceinline__ void ldsm4(uint32_t* r, uint32_t addr) {
    asm volatile("ldmatrix.sync.aligned.m8n8.x4.shared.b16 {%0,%1,%2,%3}, [%4];"
                 : "=r"(r[0]), "=r"(r[1]), "=r"(r[2]), "=r"(r[3]) : "r"(addr));
}

__device__ __forceinline__ void ldsm4t(uint32_t* r, uint32_t addr) {
    asm volatile("ldmatrix.sync.aligned.m8n8.x4.trans.shared.b16 {%0,%1,%2,%3}, [%4];"
                 : "=r"(r[0]), "=r"(r[1]), "=r"(r[2]), "=r"(r[3]) : "r"(addr));
}

__device__ __forceinline__ void mma_f16(float4& c, const uint32_t* a, uint32_t b0, uint32_t b1) {
    asm volatile(
        "mma.sync.aligned.m16n8k16.row.col.f32.f16.f16.f32 "
        "{%0,%1,%2,%3}, {%4,%5,%6,%7}, {%8,%9}, {%0,%1,%2,%3};"
        : "+f"(c.x), "+f"(c.y), "+f"(c.z), "+f"(c.w)
        : "r"(a[0]), "r"(a[1]), "r"(a[2]), "r"(a[3]), "r"(b0), "r"(b1));
}

__device__ __forceinline__ float gelu_fast(float v) {
    float z = 0.7978845608028654f * (v + 0.044715f * v * v * v);
    float t = __expf(-2.0f * z);
    return v / (1.0f + t);
}

// ---------------- small kernels ----------------
__global__ void zero_kernel() {
    int i = threadIdx.x;
    if (i < NEXP) { g_counts[i] = 0; g_cnt2[i] = 0; }
}

__global__ void router_kernel(const float* __restrict__ x, const float* __restrict__ Wr) {
    __shared__ float sW[CDIM * NEXP];
    int tid = threadIdx.x;
    for (int i = tid; i < CDIM * NEXP; i += 256) sW[i] = Wr[i];
    __syncthreads();

    int warp = tid >> 5, lane = tid & 31;
    int t = blockIdx.x * 8 + warp;
    const float* xr = x + (size_t)t * CDIM;

    float acc[NEXP];
#pragma unroll
    for (int e = 0; e < NEXP; e++) acc[e] = 0.0f;
    for (int i = lane; i < CDIM; i += 32) {
        float xv = xr[i];
#pragma unroll
        for (int e = 0; e < NEXP; e++) acc[e] += xv * sW[i * NEXP + e];
    }
#pragma unroll
    for (int off = 16; off > 0; off >>= 1)
#pragma unroll
        for (int e = 0; e < NEXP; e++) acc[e] += __shfl_xor_sync(0xffffffffu, acc[e], off);

    if (lane == 0) {
        float v0 = -3.4e38f, v1 = -3.4e38f;
        int e0 = 0, e1 = 0;
#pragma unroll
        for (int e = 0; e < NEXP; e++) {
            float v = acc[e];
            if (v > v0) { v1 = v0; e1 = e0; v0 = v; e0 = e; }
            else if (v > v1) { v1 = v; e1 = e; }
        }
        float x1 = expf(v1 - v0);
        float inv = 1.0f / (1.0f + x1);
        g_tope[2 * t] = e0;   g_tope[2 * t + 1] = e1;
        g_topg[2 * t] = inv;  g_topg[2 * t + 1] = x1 * inv;
        atomicAdd(&g_counts[e0], 1);
        atomicAdd(&g_counts[e1], 1);
    }
}

__global__ void offsets_tiles_kernel() {
    if (threadIdx.x == 0) {
        int off = 0, tt = 0;
        for (int e = 0; e < NEXP; e++) {
            g_offsets[e] = off;
            int cnt = g_counts[e];
            off += cnt;
            int mts = (cnt + 127) >> 7;
            for (int m = 0; m < mts; m++) { g_tile_e[tt] = e; g_tile_mt[tt] = m; tt++; }
        }
        g_total_tiles = tt;
    }
}

__global__ void assign_kernel() {
    int t = blockIdx.x * 256 + threadIdx.x;
    if (t >= NTOK) return;
#pragma unroll
    for (int j = 0; j < 2; j++) {
        int e = g_tope[2 * t + j];
        int slot = atomicAdd(&g_cnt2[e], 1);
        int p = g_offsets[e] + slot;
        g_pair_token[p] = t;
        g_pair_of_token[2 * t + j] = p;
    }
}

// fp32 -> fp16 bulk convert (grid-stride over float4)
__global__ void f2h_kernel(const float* __restrict__ src, __half* __restrict__ dst, int n4) {
    int i = blockIdx.x * 256 + threadIdx.x;
    if (i >= n4) return;
    float4 v = ((const float4*)src)[i];
    uint2 u;
    u.x = pk(v.x, v.y);
    u.y = pk(v.z, v.w);
    ((uint2*)dst)[i] = u;
}

// gather x rows into compacted pair order as fp16
__global__ void gather_xh_kernel(const float* __restrict__ x) {
    int p = blockIdx.x;
    int t = g_pair_token[p];
    const float4* src = (const float4*)(x + (size_t)t * CDIM);
    uint4* dst = (uint4*)(g_xh + (size_t)p * CDIM);
    int i = threadIdx.x;  // 128 threads, 8 elems each
    float4 a = src[2 * i], b = src[2 * i + 1];
    dst[i] = make_uint4(pk(a.x, a.y), pk(a.z, a.w), pk(b.x, b.y), pk(b.z, b.w));
}

// ---------------- grouped fp16 GEMM: cp.async 4-stage + mma.sync ----------------
// BM=128, BN=256, BK=32. 256 threads = 8 warps (2 M x 4 N), warp tile 64x64.
// smem/stage 24KB (A 8KB @0 + B 16KB @8192), 4 stages = 96KB dyn smem, 1 CTA/SM.
// A swizzle: chunk c2 ^= (r>>1)&3 (64B rows). B swizzle: cn ^= (k&7)^((k&1)<<2) (512B rows).
#define GSTAGES 4
#define STG_BYTES 24576
#define DYN_SMEM (GSTAGES * STG_BYTES)

template <int KDIM, int NCOLS, bool DOGELU>
__global__ __launch_bounds__(256, 1) void moe_gemm_cp(const __half* __restrict__ A,
                                                      const __half* __restrict__ B,
                                                      __half* __restrict__ Ch,
                                                      float* __restrict__ Cf) {
    int ti = blockIdx.y;
    if (ti >= g_total_tiles) return;
    int e = g_tile_e[ti], mt = g_tile_mt[ti];
    int cnt = g_counts[e];
    int row0 = g_offsets[e] + mt * 128;
    int mrows = min(128, cnt - mt * 128);
    int n0 = blockIdx.x * 256;
    const __half* Bb = B + (size_t)e * KDIM * NCOLS + n0;

    extern __shared__ __align__(128) uint8_t sm[];
    uint32_t smemBase = smem_u32(sm);

    int tid = threadIdx.x, warp = tid >> 5, lane = tid & 31;
    int wm = warp >> 2, wn = warp & 3;

    // A loader: thread t -> row ar = t>>1, chunks c2base = (t&1)*2 + {0,1}
    int ar = tid >> 1;
    int ac2 = (tid & 1) * 2;
    uint32_t aswz = (uint32_t)((ar >> 1) & 3);
    const __half* aSrc = A + (size_t)(row0 + ar) * KDIM + ac2 * 8;
    uint32_t aD0 = ar * 64 + ((((uint32_t)ac2 + 0) ^ aswz) << 4);
    uint32_t aD1 = ar * 64 + ((((uint32_t)ac2 + 1) ^ aswz) << 4);

    // B loader: thread t -> row bk = t>>3 (0..31), 4 chunks cn = (t&7) + 8j
    int bk = tid >> 3;
    int bc = tid & 7;
    uint32_t bex = (uint32_t)((bk & 7) ^ ((bk & 1) << 2));
    const __half* bSrc = Bb + (size_t)bk * NCOLS + bc * 8;
    uint32_t bD[4];
#pragma unroll
    for (int j = 0; j < 4; j++)
        bD[j] = 8192 + bk * 512 + ((((uint32_t)(bc + 8 * j)) ^ bex) << 4);

    // ldmatrix addresses (stage-relative)
    int rloc = (lane & 7) + ((lane >> 3) & 1) * 8;
    int c2b = (lane >> 4) & 1;
    uint32_t aLd[4], bLd[4];
#pragma unroll
    for (int ms = 0; ms < 4; ms++) {
        int r = wm * 64 + ms * 16 + rloc;
        aLd[ms] = r * 64 + ((uint32_t)(c2b ^ ((r >> 1) & 3)) << 4);
    }
    uint32_t bex2 = (uint32_t)((rloc & 7) ^ ((rloc & 1) << 2));
#pragma unroll
    for (int p = 0; p < 4; p++) {
        uint32_t cn = (uint32_t)(wn * 8 + p * 2 + c2b);
        bLd[p] = 8192 + rloc * 512 + ((cn ^ bex2) << 4);
    }

    float4 acc[4][8];
#pragma unroll
    for (int ms = 0; ms < 4; ms++)
#pragma unroll
        for (int ns = 0; ns < 8; ns++) acc[ms][ns] = make_float4(0.f, 0.f, 0.f, 0.f);

#define ISSUE(k0, st)                                                                  \
    {                                                                                  \
        uint32_t sb = smemBase + (st) * STG_BYTES;                                     \
        cp16(sb + aD0, aSrc + (k0));                                                   \
        cp16(sb + aD1, aSrc + (k0) + 8);                                               \
        const __half* bp = bSrc + (size_t)(k0) * NCOLS;                                \
        _Pragma("unroll") for (int j = 0; j < 4; j++)                                  \
            cp16(sb + bD[j], bp + 64 * j);                                             \
        asm volatile("cp.async.commit_group;" ::: "memory");                           \
    }

#define COMPUTE(st)                                                                    \
    {                                                                                  \
        uint32_t sb = smemBase + (st) * STG_BYTES;                                     \
        _Pragma("unroll") for (int ks = 0; ks < 2; ks++) {                             \
            uint32_t af[4][4], bf[4][4];                                               \
            _Pragma("unroll") for (int ms = 0; ms < 4; ms++)                           \
                ldsm4(af[ms], sb + (aLd[ms] ^ (ks << 5)));                             \
            _Pragma("unroll") for (int p = 0; p < 4; p++)                              \
                ldsm4t(bf[p], sb + bLd[p] + ks * 8192);                                \
            _Pragma("unroll") for (int ms = 0; ms < 4; ms++)                           \
                _Pragma("unroll") for (int p = 0; p < 4; p++) {                        \
                    mma_f16(acc[ms][2 * p], af[ms], bf[p][0], bf[p][1]);               \
                    mma_f16(acc[ms][2 * p + 1], af[ms], bf[p][2], bf[p][3]);           \
                }                                                                      \
        }                                                                              \
    }

    const int NIT = KDIM / 32;
    ISSUE(0, 0);
    ISSUE(32, 1);
    ISSUE(64, 2);
    int kIss = 3;

    for (int kt = 0; kt < NIT; kt++) {
        asm volatile("cp.async.wait_group 2;" ::: "memory");
        __syncthreads();
        if (kIss < NIT) { ISSUE(kIss * 32, kIss & 3); kIss++; }
        COMPUTE(kt & 3);
    }

    // epilogue: warp covers rows wm*64..+63, cols n0 + wn*64..+63
    int r1 = lane >> 2, cb = (lane & 3) * 2;
#pragma unroll
    for (int ms = 0; ms < 4; ms++) {
#pragma unroll
        for (int half = 0; half < 2; half++) {
            int lr = wm * 64 + ms * 16 + r1 + half * 8;
            if (lr < mrows) {
                size_t rowoff = (size_t)(row0 + lr) * NCOLS + n0 + wn * 64;
#pragma unroll
                for (int ns = 0; ns < 8; ns++) {
                    float v0 = half ? acc[ms][ns].z : acc[ms][ns].x;
                    float v1 = half ? acc[ms][ns].w : acc[ms][ns].y;
                    if (DOGELU) {
                        v0 = gelu_fast(v0);
                        v1 = gelu_fast(v1);
                        *(uint32_t*)(Ch + rowoff + ns * 8 + cb) = pk(v0, v1);
                    } else {
                        *(float2*)(Cf + rowoff + ns * 8 + cb) = make_float2(v0, v1);
                    }
                }
            }
        }
    }
#undef ISSUE
#undef COMPUTE
}

// ---------------- combine ----------------
__global__ void combine_kernel(float* __restrict__ out) {
    size_t idx = (size_t)blockIdx.x * 256 + threadIdx.x;
    int t = (int)(idx >> 8);
    int cg = (int)(idx & 255);
    int p0 = g_pair_of_token[2 * t];
    int p1 = g_pair_of_token[2 * t + 1];
    float g0 = g_topg[2 * t], g1 = g_topg[2 * t + 1];
    float4 a = *(const float4*)&g_y[(size_t)p0 * CDIM + cg * 4];
    float4 b = *(const float4*)&g_y[(size_t)p1 * CDIM + cg * 4];
    float4 r;
    r.x = g0 * a.x + g1 * b.x;
    r.y = g0 * a.y + g1 * b.y;
    r.z = g0 * a.z + g1 * b.z;
    r.w = g0 * a.w + g1 * b.w;
    ((float4*)out)[idx] = r;
}

// ---------------- launch ----------------
extern "C" void kernel_launch(void* const* d_in, const int* in_sizes, int n_in,
                              void* d_out, int out_size) {
    const float* x  = (const float*)d_in[0];  // (8192, 1024)
    const float* Wr = (const float*)d_in[1];  // (1024, 8)
    const float* W1 = (const float*)d_in[2];  // (8, 1024, 4096)
    const float* W2 = (const float*)d_in[3];  // (8, 4096, 1024)
    float* out = (float*)d_out;

    __half *h_ptr, *xh_ptr, *w1h_ptr, *w2h_ptr;
    float* y_ptr;
    cudaGetSymbolAddress((void**)&h_ptr, g_h);
    cudaGetSymbolAddress((void**)&y_ptr, g_y);
    cudaGetSymbolAddress((void**)&xh_ptr, g_xh);
    cudaGetSymbolAddress((void**)&w1h_ptr, g_w1h);
    cudaGetSymbolAddress((void**)&w2h_ptr, g_w2h);

    cudaFuncSetAttribute(moe_gemm_cp<CDIM, HDIM, true>,
                         cudaFuncAttributeMaxDynamicSharedMemorySize, DYN_SMEM);
    cudaFuncSetAttribute(moe_gemm_cp<HDIM, CDIM, false>,
                         cudaFuncAttributeMaxDynamicSharedMemorySize, DYN_SMEM);

    const int WELEM4 = NEXP * CDIM * HDIM / 4;

    zero_kernel<<<1, 32>>>();
    router_kernel<<<NTOK / 8, 256>>>(x, Wr);
    offsets_tiles_kernel<<<1, 32>>>();
    assign_kernel<<<NTOK / 256, 256>>>();
    gather_xh_kernel<<<NPAIR, 128>>>(x);
    f2h_kernel<<<(WELEM4 + 255) / 256, 256>>>(W1, w1h_ptr, WELEM4);
    f2h_kernel<<<(WELEM4 + 255) / 256, 256>>>(W2, w2h_ptr, WELEM4);
    moe_gemm_cp<CDIM, HDIM, true><<<dim3(HDIM / 256, 136), 256, DYN_SMEM>>>(xh_ptr, w1h_ptr, h_ptr, nullptr);
    moe_gemm_cp<HDIM, CDIM, false><<<dim3(CDIM / 256, 136), 256, DYN_SMEM>>>(h_ptr, w2h_ptr, nullptr, y_ptr);
    combine_kernel<<<(NTOK * CDIM / 4) / 256, 256>>>(out);
}

// round 7
// speedup vs baseline: 1.1431x; 1.1431x over previous
#include <cuda_runtime.h>
#include <cuda_fp16.h>
#include <cstdint>

#define NTOK 8192
#define CDIM 1024
#define HDIM 4096
#define NEXP 8
#define NPAIR (NTOK * 2)
#define MAXTILES 160

// ---------------- scratch (device globals; no allocs allowed) ----------------
__device__ __half g_h[(size_t)(NPAIR + 128) * HDIM];   // gelu(x@W1), fp16 (padded rows)
__device__ float  g_y[(size_t)NPAIR * CDIM];           // (h@W2) per pair
__device__ __half g_xh[(size_t)(NPAIR + 128) * CDIM];  // gathered x rows, fp16 (padded)
__device__ __half g_w1h[(size_t)NEXP * CDIM * HDIM];   // W1 fp16
__device__ __half g_w2h[(size_t)NEXP * HDIM * CDIM];   // W2 fp16
__device__ int    g_counts[NEXP];
__device__ int    g_cnt2[NEXP];
__device__ int    g_offsets[NEXP];
__device__ int    g_tope[NPAIR];
__device__ float  g_topg[NPAIR];
__device__ int    g_pair_token[NPAIR];
__device__ int    g_pair_of_token[NPAIR];
__device__ int    g_tile_e[MAXTILES];
__device__ int    g_tile_mt[MAXTILES];
__device__ int    g_total_tiles;

// ---------------- helpers ----------------
__device__ __forceinline__ uint32_t pk(float lo, float hi) {
    uint32_t u;
    asm("cvt.rn.f16x2.f32 %0, %1, %2;" : "=r"(u) : "f"(hi), "f"(lo));
    return u;
}

__device__ __forceinline__ uint32_t smem_u32(const void* p) {
    uint32_t a;
    asm("{ .reg .u64 t; cvta.to.shared.u64 t, %1; cvt.u32.u64 %0, t; }" : "=r"(a) : "l"(p));
    return a;
}

__device__ __forceinline__ void cp16(uint32_t dst, const void* src) {
    asm volatile("cp.async.cg.shared.global [%0], [%1], 16;" :: "r"(dst), "l"(src));
}

__device__ __forceinline__ void ldsm4(uint32_t* r, uint32_t addr) {
    asm volatile("ldmatrix.sync.aligned.m8n8.x4.shared.b16 {%0,%1,%2,%3}, [%4];"
                 : "=r"(r[0]), "=r"(r[1]), "=r"(r[2]), "=r"(r[3]) : "r"(addr));
}

__device__ __forceinline__ void ldsm4t(uint32_t* r, uint32_t addr) {
    asm volatile("ldmatrix.sync.aligned.m8n8.x4.trans.shared.b16 {%0,%1,%2,%3}, [%4];"
                 : "=r"(r[0]), "=r"(r[1]), "=r"(r[2]), "=r"(r[3]) : "r"(addr));
}

__device__ __forceinline__ void mma_f16(float4& c, const uint32_t* a, uint32_t b0, uint32_t b1) {
    asm volatile(
        "mma.sync.aligned.m16n8k16.row.col.f32.f16.f16.f32 "
        "{%0,%1,%2,%3}, {%4,%5,%6,%7}, {%8,%9}, {%0,%1,%2,%3};"
        : "+f"(c.x), "+f"(c.y), "+f"(c.z), "+f"(c.w)
        : "r"(a[0]), "r"(a[1]), "r"(a[2]), "r"(a[3]), "r"(b0), "r"(b1));
}

__device__ __forceinline__ float gelu_fast(float v) {
    float z = 0.7978845608028654f * (v + 0.044715f * v * v * v);
    float t = __expf(-2.0f * z);
    return v / (1.0f + t);
}

// ---------------- small kernels ----------------
__global__ void zero_kernel() {
    int i = threadIdx.x;
    if (i < NEXP) { g_counts[i] = 0; g_cnt2[i] = 0; }
}

__global__ void router_kernel(const float* __restrict__ x, const float* __restrict__ Wr) {
    __shared__ float sW[CDIM * NEXP];
    int tid = threadIdx.x;
    for (int i = tid; i < CDIM * NEXP; i += 256) sW[i] = Wr[i];
    __syncthreads();

    int warp = tid >> 5, lane = tid & 31;
    int t = blockIdx.x * 8 + warp;
    const float* xr = x + (size_t)t * CDIM;

    float acc[NEXP];
#pragma unroll
    for (int e = 0; e < NEXP; e++) acc[e] = 0.0f;
    for (int i = lane; i < CDIM; i += 32) {
        float xv = xr[i];
#pragma unroll
        for (int e = 0; e < NEXP; e++) acc[e] += xv * sW[i * NEXP + e];
    }
#pragma unroll
    for (int off = 16; off > 0; off >>= 1)
#pragma unroll
        for (int e = 0; e < NEXP; e++) acc[e] += __shfl_xor_sync(0xffffffffu, acc[e], off);

    if (lane == 0) {
        float v0 = -3.4e38f, v1 = -3.4e38f;
        int e0 = 0, e1 = 0;
#pragma unroll
        for (int e = 0; e < NEXP; e++) {
            float v = acc[e];
            if (v > v0) { v1 = v0; e1 = e0; v0 = v; e0 = e; }
            else if (v > v1) { v1 = v; e1 = e; }
        }
        float x1 = expf(v1 - v0);
        float inv = 1.0f / (1.0f + x1);
        g_tope[2 * t] = e0;   g_tope[2 * t + 1] = e1;
        g_topg[2 * t] = inv;  g_topg[2 * t + 1] = x1 * inv;
        atomicAdd(&g_counts[e0], 1);
        atomicAdd(&g_counts[e1], 1);
    }
}

__global__ void offsets_tiles_kernel() {
    if (threadIdx.x == 0) {
        int off = 0, tt = 0;
        for (int e = 0; e < NEXP; e++) {
            g_offsets[e] = off;
            int cnt = g_counts[e];
            off += cnt;
            int mts = (cnt + 127) >> 7;
            for (int m = 0; m < mts; m++) { g_tile_e[tt] = e; g_tile_mt[tt] = m; tt++; }
        }
        g_total_tiles = tt;
    }
}

__global__ void assign_kernel() {
    int t = blockIdx.x * 256 + threadIdx.x;
    if (t >= NTOK) return;
#pragma unroll
    for (int j = 0; j < 2; j++) {
        int e = g_tope[2 * t + j];
        int slot = atomicAdd(&g_cnt2[e], 1);
        int p = g_offsets[e] + slot;
        g_pair_token[p] = t;
        g_pair_of_token[2 * t + j] = p;
    }
}

// fp32 -> fp16 bulk convert (grid-stride over float4)
__global__ void f2h_kernel(const float* __restrict__ src, __half* __restrict__ dst, int n4) {
    int i = blockIdx.x * 256 + threadIdx.x;
    if (i >= n4) return;
    float4 v = ((const float4*)src)[i];
    uint2 u;
    u.x = pk(v.x, v.y);
    u.y = pk(v.z, v.w);
    ((uint2*)dst)[i] = u;
}

// gather x rows into compacted pair order as fp16
__global__ void gather_xh_kernel(const float* __restrict__ x) {
    int p = blockIdx.x;
    int t = g_pair_token[p];
    const float4* src = (const float4*)(x + (size_t)t * CDIM);
    uint4* dst = (uint4*)(g_xh + (size_t)p * CDIM);
    int i = threadIdx.x;  // 128 threads, 8 elems each
    float4 a = src[2 * i], b = src[2 * i + 1];
    dst[i] = make_uint4(pk(a.x, a.y), pk(a.z, a.w), pk(b.x, b.y), pk(b.z, b.w));
}

// ---------------- grouped fp16 GEMM: cp.async 4-stage + mma.sync ----------------
// BM=128, BN=128, BK=32. 128 threads = 4 warps (2 M x 2 N), warp tile 64x64.
// smem/stage 16KB (A 8KB @0 + B 8KB @8192), 4 stages = 64KB dyn smem, 2 CTAs/SM.
// A swizzle: chunk c2 ^= (r>>1)&3 (64B rows). B swizzle: cn ^= (k&7)^((k&1)<<2) (256B rows).
#define GSTAGES 4
#define STG_BYTES 16384
#define DYN_SMEM (GSTAGES * STG_BYTES)

template <int KDIM, int NCOLS, bool DOGELU>
__global__ __launch_bounds__(128, 2) void moe_gemm_cp(const __half* __restrict__ A,
                                                      const __half* __restrict__ B,
                                                      __half* __restrict__ Ch,
                                                      float* __restrict__ Cf) {
    int ti = blockIdx.y;
    if (ti >= g_total_tiles) return;
    int e = g_tile_e[ti], mt = g_tile_mt[ti];
    int cnt = g_counts[e];
    int row0 = g_offsets[e] + mt * 128;
    int mrows = min(128, cnt - mt * 128);
    int n0 = blockIdx.x * 128;
    const __half* Bb = B + (size_t)e * KDIM * NCOLS + n0;

    extern __shared__ __align__(128) uint8_t sm[];
    uint32_t smemBase = smem_u32(sm);

    int tid = threadIdx.x, warp = tid >> 5, lane = tid & 31;
    int wm = warp >> 1, wn = warp & 1;

    // A loader: thread t -> rows ar0=t>>1 and ar0+64; chunks c2 = (t&1)*2 + {0,1}
    int ar0 = tid >> 1;
    int ac2 = (tid & 1) * 2;
    const __half* aSrc0 = A + (size_t)(row0 + ar0) * KDIM + ac2 * 8;
    const __half* aSrc1 = A + (size_t)(row0 + ar0 + 64) * KDIM + ac2 * 8;
    uint32_t aswz0 = (uint32_t)((ar0 >> 1) & 3);
    uint32_t aswz1 = (uint32_t)(((ar0 + 64) >> 1) & 3);
    uint32_t aD00 = ar0 * 64 + ((((uint32_t)ac2 + 0) ^ aswz0) << 4);
    uint32_t aD01 = ar0 * 64 + ((((uint32_t)ac2 + 1) ^ aswz0) << 4);
    uint32_t aD10 = (ar0 + 64) * 64 + ((((uint32_t)ac2 + 0) ^ aswz1) << 4);
    uint32_t aD11 = (ar0 + 64) * 64 + ((((uint32_t)ac2 + 1) ^ aswz1) << 4);

    // B loader: thread t -> row bk = t>>2 (0..31), chunks cn = (t&3) + 4j (j=0..3)
    int bk = tid >> 2;
    int bc = tid & 3;
    uint32_t bex = (uint32_t)((bk & 7) ^ ((bk & 1) << 2));
    const __half* bSrc = Bb + (size_t)bk * NCOLS + bc * 8;
    uint32_t bD[4];
#pragma unroll
    for (int j = 0; j < 4; j++)
        bD[j] = 8192 + bk * 256 + ((((uint32_t)(bc + 4 * j)) ^ bex) << 4);

    // ldmatrix addresses (stage-relative)
    int rloc = (lane & 7) + ((lane >> 3) & 1) * 8;
    int c2b = (lane >> 4) & 1;
    uint32_t aLd[4], bLd[4];
#pragma unroll
    for (int ms = 0; ms < 4; ms++) {
        int r = wm * 64 + ms * 16 + rloc;
        aLd[ms] = r * 64 + ((uint32_t)(c2b ^ ((r >> 1) & 3)) << 4);
    }
    uint32_t bex2 = (uint32_t)((rloc & 7) ^ ((rloc & 1) << 2));
#pragma unroll
    for (int p = 0; p < 4; p++) {
        uint32_t cn = (uint32_t)(wn * 8 + p * 2 + c2b);
        bLd[p] = 8192 + rloc * 256 + ((cn ^ bex2) << 4);
    }

    float4 acc[4][8];
#pragma unroll
    for (int ms = 0; ms < 4; ms++)
#pragma unroll
        for (int ns = 0; ns < 8; ns++) acc[ms][ns] = make_float4(0.f, 0.f, 0.f, 0.f);

#define ISSUE(k0, st)                                                                  \
    {                                                                                  \
        uint32_t sb = smemBase + (st) * STG_BYTES;                                     \
        cp16(sb + aD00, aSrc0 + (k0));                                                 \
        cp16(sb + aD01, aSrc0 + (k0) + 8);                                             \
        cp16(sb + aD10, aSrc1 + (k0));                                                 \
        cp16(sb + aD11, aSrc1 + (k0) + 8);                                             \
        const __half* bp = bSrc + (size_t)(k0) * NCOLS;                                \
        _Pragma("unroll") for (int j = 0; j < 4; j++)                                  \
            cp16(sb + bD[j], bp + 32 * j);                                             \
        asm volatile("cp.async.commit_group;" ::: "memory");                           \
    }

#define COMPUTE(st)                                                                    \
    {                                                                                  \
        uint32_t sb = smemBase + (st) * STG_BYTES;                                     \
        _Pragma("unroll") for (int ks = 0; ks < 2; ks++) {                             \
            uint32_t af[4][4], bf[4][4];                                               \
            _Pragma("unroll") for (int ms = 0; ms < 4; ms++)                           \
                ldsm4(af[ms], sb + (aLd[ms] ^ (ks << 5)));                             \
            _Pragma("unroll") for (int p = 0; p < 4; p++)                              \
                ldsm4t(bf[p], sb + bLd[p] + ks * 4096);                                \
            _Pragma("unroll") for (int ms = 0; ms < 4; ms++)                           \
                _Pragma("unroll") for (int p = 0; p < 4; p++) {                        \
                    mma_f16(acc[ms][2 * p], af[ms], bf[p][0], bf[p][1]);               \
                    mma_f16(acc[ms][2 * p + 1], af[ms], bf[p][2], bf[p][3]);           \
                }                                                                      \
        }                                                                              \
    }

    const int NIT = KDIM / 32;
    ISSUE(0, 0);
    ISSUE(32, 1);
    ISSUE(64, 2);
    int kIss = 3;

    for (int kt = 0; kt < NIT; kt++) {
        asm volatile("cp.async.wait_group 2;" ::: "memory");
        __syncthreads();
        if (kIss < NIT) { ISSUE(kIss * 32, kIss & 3); kIss++; }
        COMPUTE(kt & 3);
    }

    // epilogue: warp covers rows wm*64..+63, cols n0 + wn*64..+63
    int r1 = lane >> 2, cb = (lane & 3) * 2;
#pragma unroll
    for (int ms = 0; ms < 4; ms++) {
#pragma unroll
        for (int half = 0; half < 2; half++) {
            int lr = wm * 64 + ms * 16 + r1 + half * 8;
            if (lr < mrows) {
                size_t rowoff = (size_t)(row0 + lr) * NCOLS + n0 + wn * 64;
#pragma unroll
                for (int ns = 0; ns < 8; ns++) {
                    float v0 = half ? acc[ms][ns].z : acc[ms][ns].x;
                    float v1 = half ? acc[ms][ns].w : acc[ms][ns].y;
                    if (DOGELU) {
                        v0 = gelu_fast(v0);
                        v1 = gelu_fast(v1);
                        *(uint32_t*)(Ch + rowoff + ns * 8 + cb) = pk(v0, v1);
                    } else {
                        *(float2*)(Cf + rowoff + ns * 8 + cb) = make_float2(v0, v1);
                    }
                }
            }
        }
    }
#undef ISSUE
#undef COMPUTE
}

// ---------------- combine ----------------
__global__ void combine_kernel(float* __restrict__ out) {
    size_t idx = (size_t)blockIdx.x * 256 + threadIdx.x;
    int t = (int)(idx >> 8);
    int cg = (int)(idx & 255);
    int p0 = g_pair_of_token[2 * t];
    int p1 = g_pair_of_token[2 * t + 1];
    float g0 = g_topg[2 * t], g1 = g_topg[2 * t + 1];
    float4 a = *(const float4*)&g_y[(size_t)p0 * CDIM + cg * 4];
    float4 b = *(const float4*)&g_y[(size_t)p1 * CDIM + cg * 4];
    float4 r;
    r.x = g0 * a.x + g1 * b.x;
    r.y = g0 * a.y + g1 * b.y;
    r.z = g0 * a.z + g1 * b.z;
    r.w = g0 * a.w + g1 * b.w;
    ((float4*)out)[idx] = r;
}

// ---------------- launch ----------------
extern "C" void kernel_launch(void* const* d_in, const int* in_sizes, int n_in,
                              void* d_out, int out_size) {
    const float* x  = (const float*)d_in[0];  // (8192, 1024)
    const float* Wr = (const float*)d_in[1];  // (1024, 8)
    const float* W1 = (const float*)d_in[2];  // (8, 1024, 4096)
    const float* W2 = (const float*)d_in[3];  // (8, 4096, 1024)
    float* out = (float*)d_out;

    __half *h_ptr, *xh_ptr, *w1h_ptr, *w2h_ptr;
    float* y_ptr;
    cudaGetSymbolAddress((void**)&h_ptr, g_h);
    cudaGetSymbolAddress((void**)&y_ptr, g_y);
    cudaGetSymbolAddress((void**)&xh_ptr, g_xh);
    cudaGetSymbolAddress((void**)&w1h_ptr, g_w1h);
    cudaGetSymbolAddress((void**)&w2h_ptr, g_w2h);

    cudaFuncSetAttribute(moe_gemm_cp<CDIM, HDIM, true>,
                         cudaFuncAttributeMaxDynamicSharedMemorySize, DYN_SMEM);
    cudaFuncSetAttribute(moe_gemm_cp<HDIM, CDIM, false>,
                         cudaFuncAttributeMaxDynamicSharedMemorySize, DYN_SMEM);

    const int WELEM4 = NEXP * CDIM * HDIM / 4;

    zero_kernel<<<1, 32>>>();
    router_kernel<<<NTOK / 8, 256>>>(x, Wr);
    offsets_tiles_kernel<<<1, 32>>>();
    assign_kernel<<<NTOK / 256, 256>>>();
    gather_xh_kernel<<<NPAIR, 128>>>(x);
    f2h_kernel<<<(WELEM4 + 255) / 256, 256>>>(W1, w1h_ptr, WELEM4);
    f2h_kernel<<<(WELEM4 + 255) / 256, 256>>>(W2, w2h_ptr, WELEM4);
    moe_gemm_cp<CDIM, HDIM, true><<<dim3(HDIM / 128, 136), 128, DYN_SMEM>>>(xh_ptr, w1h_ptr, h_ptr, nullptr);
    moe_gemm_cp<HDIM, CDIM, false><<<dim3(CDIM / 128, 136), 128, DYN_SMEM>>>(h_ptr, w2h_ptr, nullptr, y_ptr);
    combine_kernel<<<(NTOK * CDIM / 4) / 256, 256>>>(out);
}